// round 2
// baseline (speedup 1.0000x reference)
#include <cuda_runtime.h>
#include <math.h>

#define N 4096
#define D 128
#define NCLS 512
#define NBINS 1600
#define L 1601          // NUM_BINS + 1

#define ENC_NINF 0x007FFFFFu   // fenc(-inf)

// ---- device scratch ----
__device__ float g_sim[(size_t)N * N];   // 64 MB similarity scratch
__device__ float g_loss[N];
__device__ float g_reward[N];
__device__ int   g_cntR[NCLS];
__device__ int   g_cntL[NCLS];
__device__ unsigned g_pmax[N];
__device__ unsigned g_nmax[N];

typedef unsigned long long ull;

// order-preserving float<->uint encoding for atomicMax
__device__ __forceinline__ unsigned fenc(float x){
    unsigned u = __float_as_uint(x);
    return (u & 0x80000000u) ? ~u : (u | 0x80000000u);
}
__device__ __forceinline__ float fdec(unsigned e){
    unsigned u = (e & 0x80000000u) ? (e & 0x7FFFFFFFu) : ~e;
    return __uint_as_float(u);
}

// packed 2x fp32 FMA (SASS FFMA2) — only reachable via PTX
__device__ __forceinline__ void ffma2(ull &d, ull a, ull b){
    asm("fma.rn.f32x2 %0, %1, %2, %0;" : "+l"(d) : "l"(a), "l"(b));
}
__device__ __forceinline__ float f2lo(ull v){ return __uint_as_float((unsigned)v); }
__device__ __forceinline__ float f2hi(ull v){ return __uint_as_float((unsigned)(v >> 32)); }

// ---------------- kernel 0: init + class counts ----------------
__global__ void init_kernel(const int* __restrict__ tr, const int* __restrict__ rl){
    __shared__ int cR[NCLS], cL[NCLS];
    int t = threadIdx.x;
    for (int i = t; i < NCLS; i += 1024){ cR[i] = 0; cL[i] = 0; }
    __syncthreads();
    for (int i = t; i < N; i += 1024){
        atomicAdd(&cR[tr[i]], 1);
        atomicAdd(&cL[rl[i]], 1);
        g_pmax[i] = ENC_NINF;
        g_nmax[i] = ENC_NINF;
    }
    __syncthreads();
    for (int i = t; i < NCLS; i += 1024){ g_cntR[i] = cR[i]; g_cntL[i] = cL[i]; }
}

// ---------------- kernel 1: loss GEMM (128x128 tiles, f32x2) ----------------
#define LKC 16

__global__ __launch_bounds__(256, 2) void loss_gemm(
    const float* __restrict__ A, const int* __restrict__ tc,
    const float* __restrict__ B, const int* __restrict__ tr)
{
    __shared__ __align__(16) float As[LKC][260];   // duplicated pairs: [kk][2*row+{0,1}]
    __shared__ __align__(16) float Bs[LKC][132];   // swizzled col groups
    __shared__ int tcs[128], trs[128];
    __shared__ unsigned pme[128], nme[128];

    const int tid = threadIdx.x;
    const int tx  = tid & 15;    // col group (8 cols)
    const int ty  = tid >> 4;    // row group (8 rows)
    const int row0 = blockIdx.y * 128;
    const int col0 = blockIdx.x * 128;

    if (tid < 128){
        tcs[tid] = tc[row0 + tid];
        trs[tid] = tr[col0 + tid];
        pme[tid] = ENC_NINF;
        nme[tid] = ENC_NINF;
    }

    ull acc[8][4];
#pragma unroll
    for (int r = 0; r < 8; r++)
#pragma unroll
        for (int c = 0; c < 4; c++) acc[r][c] = 0ULL;

    for (int kc = 0; kc < D; kc += LKC){
        // A tile, duplicated: 128 rows x 16 k
#pragma unroll
        for (int it = 0; it < 8; it++){
            int i = tid + it * 256;
            int kk = i & 15, row = i >> 4;
            float v = A[(size_t)(row0 + row) * D + kc + kk];
            As[kk][2*row]   = v;
            As[kk][2*row+1] = v;
        }
        // B tile (transposed, group-swizzled by k4 to avoid STS conflicts)
#pragma unroll
        for (int it = 0; it < 2; it++){
            int i = tid + it * 256;
            int col = i >> 2, k4 = i & 3;
            float4 v = *(const float4*)&B[(size_t)(col0 + col) * D + kc + k4 * 4];
            int pc = (((col >> 3) ^ k4) & 15) * 8 + (col & 7);
            Bs[k4*4+0][pc] = v.x; Bs[k4*4+1][pc] = v.y;
            Bs[k4*4+2][pc] = v.z; Bs[k4*4+3][pc] = v.w;
        }
        __syncthreads();
#pragma unroll
        for (int kk = 0; kk < LKC; kk++){
            int bg = (tx ^ ((kk >> 2) & 3));
            const ulonglong2* bp = (const ulonglong2*)&Bs[kk][bg * 8];
            ulonglong2 b01 = bp[0];
            ulonglong2 b23 = bp[1];
#pragma unroll
            for (int r = 0; r < 8; r++){
                ull a2 = *(const ull*)&As[kk][2*(ty*8+r)];
                ffma2(acc[r][0], a2, b01.x);
                ffma2(acc[r][1], a2, b01.y);
                ffma2(acc[r][2], a2, b23.x);
                ffma2(acc[r][3], a2, b23.y);
            }
        }
        __syncthreads();
    }

    // epilogue: per-row maxima + sim store
#pragma unroll
    for (int r = 0; r < 8; r++){
        int lrow = ty * 8 + r;
        int gi   = row0 + lrow;
        int tcv  = tcs[lrow];
        float s[8];
#pragma unroll
        for (int c = 0; c < 4; c++){ s[2*c] = f2lo(acc[r][c]); s[2*c+1] = f2hi(acc[r][c]); }
        float pm = -INFINITY, nm = -INFINITY;
#pragma unroll
        for (int c = 0; c < 8; c++){
            int j = col0 + tx * 8 + c;
            if (trs[tx*8+c] == tcv){
                if (j != gi) pm = fmaxf(pm, s[c]);
            } else {
                nm = fmaxf(nm, s[c]);
            }
        }
        float* dst = g_sim + (size_t)gi * N + col0 + tx * 8;
        *(float4*)dst       = make_float4(s[0], s[1], s[2], s[3]);
        *(float4*)(dst + 4) = make_float4(s[4], s[5], s[6], s[7]);
        atomicMax(&pme[lrow], fenc(pm));
        atomicMax(&nme[lrow], fenc(nm));
    }
    __syncthreads();
    if (tid < 128){
        atomicMax(&g_pmax[row0 + tid], pme[tid]);
        atomicMax(&g_nmax[row0 + tid], nme[tid]);
    }
}

// ---------------- kernel 2: loss threshold pass ----------------
__global__ __launch_bounds__(256) void loss_pass2(
    const int* __restrict__ tc, const int* __restrict__ tr)
{
    __shared__ float nthr[16], pthr[16], acc_s[16];
    __shared__ int tcs[16];
    const int tid  = threadIdx.x;
    const int row0 = blockIdx.x * 16;

    if (tid < 16){
        float pm = fdec(g_pmax[row0 + tid]);
        float nm = fdec(g_nmax[row0 + tid]);
        nthr[tid]  = nm + 0.1f;                // pos selected iff sim < neg_max + margin
        pthr[tid]  = fmaxf(0.6f, pm) - 0.1f;   // neg selected iff sim > max(0.6,pos_max)-margin
        tcs[tid]   = tc[row0 + tid];
        acc_s[tid] = 0.f;
    }
    __syncthreads();

    float a[16];
#pragma unroll
    for (int r = 0; r < 16; r++) a[r] = 0.f;

    for (int j = tid; j < N; j += 256){
        int lbl = tr[j];
#pragma unroll
        for (int r = 0; r < 16; r++){
            float s = g_sim[(size_t)(row0 + r) * N + j];
            if (lbl == tcs[r]){
                if (j != row0 + r && s < nthr[r]) a[r] += 1.0f - s;
            } else if (s > pthr[r]){
                a[r] += s;
            }
        }
    }
#pragma unroll
    for (int r = 0; r < 16; r++) atomicAdd(&acc_s[r], a[r]);
    __syncthreads();
    if (tid < 16){
        int gi   = row0 + tid;
        int tcv  = tcs[tid];
        int npos = g_cntR[tcv] - ((tr[gi] == tcv) ? 1 : 0);
        g_loss[gi] = (npos > 0) ? acc_s[tid] : 0.f;
    }
}

// ---------------- kernel 3: FastAP rewards ----------------
// 8 rows/block. GEMM (f32x2) + packed u64 fixed-point histogram (1 atomic/pair).
#define RROWS 8
#define RCOLS 512
#define RKC   16
#define HEW   801     // hE words/row: word k = bins (2k, 2k+1)
#define HOW   800     // hO words/row: word k = bins (2k+1, 2k+2)
#define FPSCALE 262144.0f
#define INV_FPS (1.0f/262144.0f)

// byte offsets into dynamic smem
#define OFF_HE  0
#define OFF_HO  (OFF_HE + RROWS*HEW*8)            // 51264
#define OFF_HP  (OFF_HO + RROWS*HOW*8)            // 102464
#define OFF_BS  (OFF_HP + RROWS*1604*4)           // 153792
#define OFF_AS  (OFF_BS + RKC*520*4)              // 187072
#define OFF_RLS (OFF_AS + RKC*20*4)               // 188352
#define OFF_RLR (OFF_RLS + RCOLS*4)               // 190400
#define RSMEM_BYTES (OFF_RLR + RROWS*4)           // 190432

__global__ __launch_bounds__(256) void reward_kernel(
    const float* __restrict__ X, const int* __restrict__ rl)
{
    extern __shared__ __align__(16) unsigned char smem[];
    ull*   hE    = (ull*)(smem + OFF_HE);
    ull*   hO    = (ull*)(smem + OFF_HO);
    float* hp    = (float*)(smem + OFF_HP);
    float* Bs    = (float*)(smem + OFF_BS);   // [RKC][520]
    float* As    = (float*)(smem + OFF_AS);   // [RKC][20] duplicated pairs
    int*   rls   = (int*)(smem + OFF_RLS);
    int*   rlrow = (int*)(smem + OFF_RLR);

    const int tid  = threadIdx.x;
    const int tx   = tid & 63;    // col group (8 cols)
    const int ty   = tid >> 6;    // row pair (rows 2ty, 2ty+1)
    const int row0 = blockIdx.x * RROWS;

    for (int i = tid; i < RROWS * (HEW + HOW); i += 256){
        ((ull*)(smem + OFF_HE))[i] = 0ULL;   // zeros hE then hO (contiguous)
    }
    for (int i = tid; i < RROWS * 1604; i += 256) hp[i] = 0.f;
    if (tid < RROWS) rlrow[tid] = rl[row0 + tid];
    __syncthreads();

    for (int jt = 0; jt < N; jt += RCOLS){
        rls[tid]       = rl[jt + tid];
        rls[tid + 256] = rl[jt + tid + 256];

        ull acc[2][4];
#pragma unroll
        for (int r = 0; r < 2; r++)
#pragma unroll
            for (int c = 0; c < 4; c++) acc[r][c] = 0ULL;

        for (int kc = 0; kc < D; kc += RKC){
            if (tid < 128){
                int kk = tid & 15, row = tid >> 4;
                float v = X[(size_t)(row0 + row) * D + kc + kk];
                As[kk*20 + 2*row]   = v;
                As[kk*20 + 2*row+1] = v;
            }
#pragma unroll
            for (int it = 0; it < 8; it++){
                int i = tid + it * 256;
                int col = i >> 2, k4 = i & 3;
                float4 v = *(const float4*)&X[(size_t)(jt + col) * D + kc + k4 * 4];
                int pc = (((col >> 3) ^ k4) & 63) * 8 + (col & 7);
                Bs[(k4*4+0)*520 + pc] = v.x; Bs[(k4*4+1)*520 + pc] = v.y;
                Bs[(k4*4+2)*520 + pc] = v.z; Bs[(k4*4+3)*520 + pc] = v.w;
            }
            __syncthreads();
#pragma unroll
            for (int kk = 0; kk < RKC; kk++){
                int bg = (tx ^ ((kk >> 2) & 3));
                const ulonglong2* bp = (const ulonglong2*)&Bs[kk*520 + bg*8];
                ulonglong2 b01 = bp[0];
                ulonglong2 b23 = bp[1];
                ull a0 = *(const ull*)&As[kk*20 + 4*ty];
                ull a1 = *(const ull*)&As[kk*20 + 4*ty + 2];
                ffma2(acc[0][0], a0, b01.x); ffma2(acc[0][1], a0, b01.y);
                ffma2(acc[0][2], a0, b23.x); ffma2(acc[0][3], a0, b23.y);
                ffma2(acc[1][0], a1, b01.x); ffma2(acc[1][1], a1, b01.y);
                ffma2(acc[1][2], a1, b23.x); ffma2(acc[1][3], a1, b23.y);
            }
            __syncthreads();
        }

        // epilogue: packed histogram scatter (1 u64 atomic per pair)
#pragma unroll
        for (int r = 0; r < 2; r++){
            int lrow = 2 * ty + r;
            int gi   = row0 + lrow;
            int li   = rlrow[lrow];
#pragma unroll
            for (int c = 0; c < 4; c++){
                float sv[2] = { f2lo(acc[r][c]), f2hi(acc[r][c]) };
#pragma unroll
                for (int e = 0; e < 2; e++){
                    int j = jt + tx * 8 + 2 * c + e;
                    if (j == gi) continue;
                    float s  = sv[e];
                    float d2 = fminf(fmaxf(2.0f - 2.0f * s, 0.0f), 4.0f);
                    float t  = d2 * 400.0f;
                    float fl = floorf(t);
                    int   i0 = (int)fl;
                    float fr = t - fl;
                    unsigned w1 = (unsigned)(fr * FPSCALE + 0.5f);
                    unsigned w0 = 262144u - w1;
                    if (i0 >= NBINS){
                        atomicAdd(&hE[lrow*HEW + 800], (ull)(w0 + w1));
                    } else if (i0 & 1){
                        atomicAdd(&hO[lrow*HOW + ((i0-1) >> 1)], (ull)w0 | ((ull)w1 << 32));
                    } else {
                        atomicAdd(&hE[lrow*HEW + (i0 >> 1)],     (ull)w0 | ((ull)w1 << 32));
                    }
                    if (rls[tx*8 + 2*c + e] == li){
                        int i1 = (i0 >= NBINS) ? NBINS : i0 + 1;
                        atomicAdd(&hp[lrow*1604 + i0], 1.0f - fr);
                        atomicAdd(&hp[lrow*1604 + i1], fr);
                    }
                }
            }
        }
        __syncthreads();   // protect rls before next tile overwrites
    }

    // per-row prefix scan + AP (warp w handles row w)
    const int warp = tid >> 5;
    const int lane = tid & 31;
    const ull*   he = hE + warp * HEW;
    const ull*   ho = hO + warp * HOW;
    const float* ph = hp + warp * 1604;
    float cp = 0.f, cs = 0.f, ap = 0.f;
    for (int base = 0; base < L; base += 32){
        int b = base + lane;
        float pv = 0.f, av = 0.f;
        if (b < L){
            pv = ph[b];
            ull we = he[b >> 1];
            unsigned u = (b & 1) ? (unsigned)(we >> 32) : (unsigned)we;
            float q = (float)u;
            if (b & 1)       q += (float)(unsigned)ho[(b - 1) >> 1];
            else if (b >= 2) q += (float)(unsigned)(ho[(b - 2) >> 1] >> 32);
            av = q * INV_FPS;   // = h_pos + h_neg (quantized)
        }
        float P = pv, S = av;
#pragma unroll
        for (int o = 1; o < 32; o <<= 1){
            float tP = __shfl_up_sync(0xFFFFFFFFu, P, o);
            float tS = __shfl_up_sync(0xFFFFFFFFu, S, o);
            if (lane >= o){ P += tP; S += tS; }
        }
        float Hp = cp + P;
        float Ha = cs + S;
        if (b < L && Ha > 0.f) ap += pv * Hp / Ha;
        cp += __shfl_sync(0xFFFFFFFFu, P, 31);
        cs += __shfl_sync(0xFFFFFFFFu, S, 31);
    }
#pragma unroll
    for (int o = 16; o; o >>= 1) ap += __shfl_down_sync(0xFFFFFFFFu, ap, o);
    if (lane == 0){
        int np = g_cntL[rlrow[warp]] - 1;
        g_reward[row0 + warp] = (np > 0) ? ap / (float)np : 0.f;
    }
}

// ---------------- kernel 4: final scalar ----------------
__global__ void final_kernel(float* __restrict__ out){
    __shared__ float red[32];
    float s = 0.f;
    for (int i = threadIdx.x; i < N; i += blockDim.x)
        s += g_loss[i] * (1.0f - g_reward[i]);
#pragma unroll
    for (int o = 16; o; o >>= 1) s += __shfl_down_sync(0xFFFFFFFFu, s, o);
    int warp = threadIdx.x >> 5, lane = threadIdx.x & 31;
    if (lane == 0) red[warp] = s;
    __syncthreads();
    if (warp == 0){
        s = (lane < (int)(blockDim.x >> 5)) ? red[lane] : 0.f;
#pragma unroll
        for (int o = 16; o; o >>= 1) s += __shfl_down_sync(0xFFFFFFFFu, s, o);
        if (lane == 0) out[0] = s / (float)N;
    }
}

// ---------------- launch ----------------
extern "C" void kernel_launch(void* const* d_in, const int* in_sizes, int n_in,
                              void* d_out, int out_size)
{
    const float* inputs_col    = (const float*)d_in[0];
    const int*   targets_col   = (const int*)  d_in[1];
    const float* inputs_row    = (const float*)d_in[2];
    const int*   targets_row   = (const int*)  d_in[3];
    const int*   reward_labels = (const int*)  d_in[4];
    float* out = (float*)d_out;

    cudaFuncSetAttribute(reward_kernel,
                         cudaFuncAttributeMaxDynamicSharedMemorySize, RSMEM_BYTES);

    init_kernel<<<1, 1024>>>(targets_row, reward_labels);
    loss_gemm<<<dim3(32, 32), 256>>>(inputs_col, targets_col, inputs_row, targets_row);
    loss_pass2<<<N / 16, 256>>>(targets_col, targets_row);
    reward_kernel<<<N / RROWS, 256, RSMEM_BYTES>>>(inputs_col, reward_labels);
    final_kernel<<<1, 256>>>(out);
}

// round 3
// speedup vs baseline: 2.8959x; 2.8959x over previous
#include <cuda_runtime.h>
#include <math.h>

#define N 4096
#define D 128
#define NCLS 512
#define NBINS 1600
#define L 1601
#define MAXP 128
#define FPS 262144.0f
#define INV_FPS (1.0f/262144.0f)

typedef unsigned long long ull;

// ---- device scratch ----
__device__ float g_sim[(size_t)N * N];   // 64 MB, reused by both GEMMs
__device__ float g_loss[N];
__device__ float g_reward[N];
__device__ int   g_cntR[NCLS], g_cntL[NCLS];
__device__ int   g_startR[NCLS + 1], g_startL[NCLS + 1];
__device__ int   g_memR[N], g_memL[N];
__device__ float g_posv[(size_t)N * MAXP];
__device__ int   g_posn[N];

// order-preserving float<->uint for atomicMax
__device__ __forceinline__ unsigned fenc(float x){
    unsigned u = __float_as_uint(x);
    return (u & 0x80000000u) ? ~u : (u | 0x80000000u);
}
__device__ __forceinline__ float fdec(unsigned e){
    unsigned u = (e & 0x80000000u) ? (e & 0x7FFFFFFFu) : ~e;
    return __uint_as_float(u);
}

// packed fp32x2 FMA (FFMA2) + broadcast-pack
__device__ __forceinline__ void ffma2(ull &d, ull a, ull b){
    asm("fma.rn.f32x2 %0, %1, %2, %0;" : "+l"(d) : "l"(a), "l"(b));
}
__device__ __forceinline__ ull dup2(float a){
    ull r; unsigned u = __float_as_uint(a);
    asm("mov.b64 %0, {%1, %1};" : "=l"(r) : "r"(u));
    return r;
}
__device__ __forceinline__ float f2lo(ull v){ return __uint_as_float((unsigned)v); }
__device__ __forceinline__ float f2hi(ull v){ return __uint_as_float((unsigned)(v >> 32)); }

// ---------------- kernel 0: counts + class CSR ----------------
__global__ void setup_kernel(const int* __restrict__ tr, const int* __restrict__ rl){
    __shared__ int cR[NCLS], cL[NCLS];
    int t = threadIdx.x;           // blockDim = 512 = NCLS
    cR[t] = 0; cL[t] = 0;
    __syncthreads();
    for (int i = t; i < N; i += 512){
        atomicAdd(&cR[tr[i]], 1);
        atomicAdd(&cL[rl[i]], 1);
    }
    __syncthreads();
    if (t == 0){
        int r = 0, l = 0;
        for (int c = 0; c < NCLS; c++){
            g_startR[c] = r; g_startL[c] = l;
            g_cntR[c] = cR[c]; g_cntL[c] = cL[c];
            r += cR[c]; l += cL[c];
        }
        g_startR[NCLS] = r; g_startL[NCLS] = l;
    }
    __syncthreads();
    cR[t] = g_startR[t]; cL[t] = g_startL[t];
    __syncthreads();
    for (int i = t; i < N; i += 512){
        int p = atomicAdd(&cR[tr[i]], 1); g_memR[p] = i;
        int q = atomicAdd(&cL[rl[i]], 1); g_memL[q] = i;
    }
}

// ---------------- pure GEMM: g_sim = A @ B^T (both [4096][128]) ----------------
__global__ __launch_bounds__(256, 2) void gemm_nt(
    const float* __restrict__ A, const float* __restrict__ B)
{
    __shared__ __align__(16) float As[128][20];
    __shared__ __align__(16) float Bs[16][132];

    const int tid = threadIdx.x;
    const int tx  = tid & 15;     // col group (8 cols)
    const int ty  = tid >> 4;     // row group (8 rows)
    const int row0 = blockIdx.y * 128;
    const int col0 = blockIdx.x * 128;
    const int lr = tid >> 2;           // load row/col 0..63
    const int lk = (tid & 3) * 4;      // k offset within 16-chunk

    ull acc[8][4];
#pragma unroll
    for (int r = 0; r < 8; r++)
#pragma unroll
        for (int c = 0; c < 4; c++) acc[r][c] = 0ULL;

    const float* Ap0 = A + (size_t)(row0 + lr) * D + lk;
    const float* Ap1 = A + (size_t)(row0 + lr + 64) * D + lk;
    const float* Bp0 = B + (size_t)(col0 + lr) * D + lk;
    const float* Bp1 = B + (size_t)(col0 + lr + 64) * D + lk;

    float4 pa0 = *(const float4*)Ap0;
    float4 pa1 = *(const float4*)Ap1;
    float4 pb0 = *(const float4*)Bp0;
    float4 pb1 = *(const float4*)Bp1;

#pragma unroll
    for (int kc = 0; kc < D; kc += 16){
        __syncthreads();
        *(float4*)&As[lr][lk]      = pa0;
        *(float4*)&As[lr + 64][lk] = pa1;
        Bs[lk+0][lr] = pb0.x; Bs[lk+1][lr] = pb0.y;
        Bs[lk+2][lr] = pb0.z; Bs[lk+3][lr] = pb0.w;
        Bs[lk+0][lr+64] = pb1.x; Bs[lk+1][lr+64] = pb1.y;
        Bs[lk+2][lr+64] = pb1.z; Bs[lk+3][lr+64] = pb1.w;
        __syncthreads();
        if (kc < D - 16){
            pa0 = *(const float4*)(Ap0 + kc + 16);
            pa1 = *(const float4*)(Ap1 + kc + 16);
            pb0 = *(const float4*)(Bp0 + kc + 16);
            pb1 = *(const float4*)(Bp1 + kc + 16);
        }
#pragma unroll
        for (int kk = 0; kk < 16; kk++){
            ulonglong2 b01 = *(const ulonglong2*)&Bs[kk][tx * 8];
            ulonglong2 b23 = *(const ulonglong2*)&Bs[kk][tx * 8 + 4];
#pragma unroll
            for (int r = 0; r < 8; r++){
                ull a2 = dup2(As[ty * 8 + r][kk]);
                ffma2(acc[r][0], a2, b01.x);
                ffma2(acc[r][1], a2, b01.y);
                ffma2(acc[r][2], a2, b23.x);
                ffma2(acc[r][3], a2, b23.y);
            }
        }
    }

#pragma unroll
    for (int r = 0; r < 8; r++){
        float o[8];
#pragma unroll
        for (int c = 0; c < 4; c++){ o[2*c] = f2lo(acc[r][c]); o[2*c+1] = f2hi(acc[r][c]); }
        float* dst = g_sim + (size_t)(row0 + ty * 8 + r) * N + col0 + tx * 8;
        *(float4*)dst       = make_float4(o[0], o[1], o[2], o[3]);
        *(float4*)(dst + 4) = make_float4(o[4], o[5], o[6], o[7]);
    }
}

// ---------------- loss fix: extract pos sims, poison them in g_sim ----------------
__global__ void loss_fix(const int* __restrict__ tc, const int* __restrict__ tr){
    const int warp = threadIdx.x >> 5, lane = threadIdx.x & 31;
    const int i = blockIdx.x * 8 + warp;
    const int c = tc[i];
    const int s0 = g_startR[c], cnt = g_startR[c + 1] - s0;
    int ki = -1;
    for (int k = lane; k < cnt; k += 32)
        if (g_memR[s0 + k] == i) ki = k;
#pragma unroll
    for (int o = 16; o; o >>= 1) ki = max(ki, __shfl_xor_sync(0xffffffffu, ki, o));
    for (int k = lane; k < cnt; k += 32){
        int j = g_memR[s0 + k];
        float v = g_sim[(size_t)i * N + j];
        g_sim[(size_t)i * N + j] = -INFINITY;
        if (j != i){
            int slot = k - ((ki >= 0 && k > ki) ? 1 : 0);
            if (slot < MAXP) g_posv[(size_t)i * MAXP + slot] = v;
        }
    }
    if (lane == 0) g_posn[i] = min(cnt - (ki >= 0 ? 1 : 0), MAXP);
}

// ---------------- loss pass: per-row max then thresholded sums ----------------
__global__ __launch_bounds__(256) void loss_pass(
    const int* __restrict__ tc, const int* __restrict__ tr)
{
    __shared__ unsigned nme[8];
    __shared__ float nthr_s[8], pthr_s[8], accs[8];
    const int tid = threadIdx.x;
    const int row0 = blockIdx.x * 8;

    if (tid < 8){ nme[tid] = fenc(-INFINITY); accs[tid] = 0.f; }
    __syncthreads();

    float m[8];
#pragma unroll
    for (int r = 0; r < 8; r++) m[r] = -INFINITY;
    for (int it = 0; it < 4; it++){
        int j4 = tid + it * 256;
#pragma unroll
        for (int r = 0; r < 8; r++){
            float4 v = *((const float4*)(g_sim + (size_t)(row0 + r) * N) + j4);
            m[r] = fmaxf(m[r], fmaxf(fmaxf(v.x, v.y), fmaxf(v.z, v.w)));
        }
    }
#pragma unroll
    for (int r = 0; r < 8; r++) atomicMax(&nme[r], fenc(m[r]));
    __syncthreads();

    if (tid < 8){
        int i = row0 + tid;
        nthr_s[tid] = fdec(nme[tid]) + 0.1f;
        float pm = -INFINITY;
        int n = g_posn[i];
        for (int k = 0; k < n; k++) pm = fmaxf(pm, g_posv[(size_t)i * MAXP + k]);
        pthr_s[tid] = fmaxf(0.6f, pm) - 0.1f;
    }
    __syncthreads();

    float pt[8], a[8];
#pragma unroll
    for (int r = 0; r < 8; r++){ pt[r] = pthr_s[r]; a[r] = 0.f; }
    for (int it = 0; it < 4; it++){
        int j4 = tid + it * 256;
#pragma unroll
        for (int r = 0; r < 8; r++){
            float4 v = *((const float4*)(g_sim + (size_t)(row0 + r) * N) + j4);
            if (v.x > pt[r]) a[r] += v.x;
            if (v.y > pt[r]) a[r] += v.y;
            if (v.z > pt[r]) a[r] += v.z;
            if (v.w > pt[r]) a[r] += v.w;
        }
    }
#pragma unroll
    for (int r = 0; r < 8; r++) atomicAdd(&accs[r], a[r]);
    __syncthreads();

    if (tid < 8){
        int i = row0 + tid;
        float pl = 0.f, nthr = nthr_s[tid];
        int n = g_posn[i];
        for (int k = 0; k < n; k++){
            float v = g_posv[(size_t)i * MAXP + k];
            if (v < nthr) pl += 1.0f - v;
        }
        int npos = g_cntR[tc[i]] - ((tr[i] == tc[i]) ? 1 : 0);
        g_loss[i] = (npos > 0) ? accs[tid] + pl : 0.f;
    }
}

// ---------------- reward histogram + AP (1 row per block) ----------------
__global__ __launch_bounds__(256) void reward_hist(const int* __restrict__ rl){
    __shared__ ull   hist[L + 1];       // per bin: hi = count, lo = frac*2^18
    __shared__ float cumf[L + 1];       // inclusive cumsum of counts
    __shared__ int   eP[MAXP];
    __shared__ float frP[MAXP];
    __shared__ int   nposs_s;
    __shared__ float s_ap;
    __shared__ unsigned wsum[8], wexc[8];

    const int tid = threadIdx.x, lane = tid & 31, warp = tid >> 5;
    const int i = blockIdx.x;

    for (int b = tid; b < L + 1; b += 256) hist[b] = 0ULL;
    if (tid == 0){ nposs_s = 0; s_ap = 0.f; }
    __syncthreads();

    const int c = rl[i];
    const float* row = g_sim + (size_t)i * N;

    // gather positive pairs via class CSR
    {
        int s0 = g_startL[c], cnt = g_startL[c + 1] - s0;
        if (tid < cnt){
            int j = g_memL[s0 + tid];
            if (j != i){
                float s = row[j];
                float t2 = fmaf(s, -800.f, 800.f);
                t2 = fminf(fmaxf(t2, 0.f), 1600.f);
                int e = (int)t2;
                float fr = t2 - (float)e;
                int k = atomicAdd(&nposs_s, 1);
                if (k < MAXP){ eP[k] = e; frP[k] = fr; }
            }
        }
    }

    // stream all j != i into the packed histogram (1 u64 atomic per item)
    const int dj4 = i >> 2;
    for (int it = 0; it < 4; it++){
        int j4 = tid + it * 256;
        float4 v = *((const float4*)row + j4);
        float sv[4] = {v.x, v.y, v.z, v.w};
        if (j4 != dj4){
#pragma unroll
            for (int e4 = 0; e4 < 4; e4++){
                float t2 = fmaf(sv[e4], -800.f, 800.f);
                t2 = fminf(fmaxf(t2, 0.f), 1600.f);
                int e = (int)t2;
                float fr = t2 - (float)e;
                unsigned w = (unsigned)(fr * FPS);
                atomicAdd(&hist[e], ((ull)1 << 32) | (ull)w);
            }
        } else {
#pragma unroll
            for (int e4 = 0; e4 < 4; e4++){
                if ((j4 * 4 + e4) == i) continue;
                float t2 = fmaf(sv[e4], -800.f, 800.f);
                t2 = fminf(fmaxf(t2, 0.f), 1600.f);
                int e = (int)t2;
                float fr = t2 - (float)e;
                unsigned w = (unsigned)(fr * FPS);
                atomicAdd(&hist[e], ((ull)1 << 32) | (ull)w);
            }
        }
    }
    __syncthreads();

    // block scan of counts -> cumf
    unsigned pre[7]; unsigned ssum = 0;
    const int b0 = tid * 7;
#pragma unroll
    for (int k = 0; k < 7; k++){
        int b = b0 + k;
        unsigned h = (b < L + 1) ? (unsigned)(hist[b] >> 32) : 0u;
        ssum += h; pre[k] = ssum;
    }
    unsigned vsc = ssum;
#pragma unroll
    for (int o = 1; o < 32; o <<= 1){
        unsigned u = __shfl_up_sync(0xffffffffu, vsc, o);
        if (lane >= o) vsc += u;
    }
    if (lane == 31) wsum[warp] = vsc;
    __syncthreads();
    if (tid == 0){
        unsigned run = 0;
        for (int w2 = 0; w2 < 8; w2++){ wexc[w2] = run; run += wsum[w2]; }
    }
    __syncthreads();
    unsigned base = wexc[warp] + (vsc - ssum);
#pragma unroll
    for (int k = 0; k < 7; k++){
        int b = b0 + k;
        if (b < L + 1) cumf[b] = (float)(base + pre[k]);
    }
    __syncthreads();

    // AP over positive pairs only
    int nposs = min(nposs_s, MAXP);
    if (tid < nposs){
        int e = eP[tid]; float fr = frP[tid];
        float HP0 = 0.f, HP1 = 0.f;
        for (int q = 0; q < nposs; q++){
            int eq = eP[q]; float g = 1.0f - frP[q];
            HP0 += (eq < e)  ? 1.0f : ((eq == e)     ? g : 0.0f);
            HP1 += (eq <= e) ? 1.0f : ((eq == e + 1) ? g : 0.0f);
        }
        float HA0 = cumf[e] - (float)(unsigned)hist[e] * INV_FPS;
        float term = 0.f;
        if (HA0 > 0.f) term += (1.0f - fr) * HP0 / HA0;
        if (fr > 0.f){
            float HA1 = cumf[e + 1] - (float)(unsigned)hist[e + 1] * INV_FPS;
            if (HA1 > 0.f) term += fr * HP1 / HA1;
        }
        atomicAdd(&s_ap, term);
    }
    __syncthreads();
    if (tid == 0){
        int np = g_cntL[c] - 1;
        g_reward[i] = (np > 0) ? s_ap / (float)np : 0.f;
    }
}

// ---------------- final scalar ----------------
__global__ void final_kernel(float* __restrict__ out){
    __shared__ float red[32];
    float s = 0.f;
    for (int i = threadIdx.x; i < N; i += blockDim.x)
        s += g_loss[i] * (1.0f - g_reward[i]);
#pragma unroll
    for (int o = 16; o; o >>= 1) s += __shfl_down_sync(0xFFFFFFFFu, s, o);
    int warp = threadIdx.x >> 5, lane = threadIdx.x & 31;
    if (lane == 0) red[warp] = s;
    __syncthreads();
    if (warp == 0){
        s = (lane < (int)(blockDim.x >> 5)) ? red[lane] : 0.f;
#pragma unroll
        for (int o = 16; o; o >>= 1) s += __shfl_down_sync(0xFFFFFFFFu, s, o);
        if (lane == 0) out[0] = s / (float)N;
    }
}

// ---------------- launch ----------------
extern "C" void kernel_launch(void* const* d_in, const int* in_sizes, int n_in,
                              void* d_out, int out_size)
{
    const float* inputs_col    = (const float*)d_in[0];
    const int*   targets_col   = (const int*)  d_in[1];
    const float* inputs_row    = (const float*)d_in[2];
    const int*   targets_row   = (const int*)  d_in[3];
    const int*   reward_labels = (const int*)  d_in[4];
    float* out = (float*)d_out;

    setup_kernel<<<1, 512>>>(targets_row, reward_labels);
    gemm_nt<<<dim3(32, 32), 256>>>(inputs_col, inputs_row);
    loss_fix<<<512, 256>>>(targets_col, targets_row);
    loss_pass<<<512, 256>>>(targets_col, targets_row);
    gemm_nt<<<dim3(32, 32), 256>>>(inputs_col, inputs_col);
    reward_hist<<<4096, 256>>>(reward_labels);
    final_kernel<<<1, 256>>>(out);
}

// round 4
// speedup vs baseline: 3.2035x; 1.1062x over previous
#include <cuda_runtime.h>
#include <math.h>

#define N 4096
#define D 128
#define NCLS 512
#define MAXP 128     // loss pos-list cap
#define MAXPR 64     // reward pos-list cap (Poisson(8) tail << 64)

typedef unsigned long long ull;

// ---- device scratch ----
__device__ float g_sim[(size_t)N * N];   // 64 MB, reused by both GEMMs
__device__ float g_loss[N];
__device__ float g_reward[N];
__device__ int   g_cntR[NCLS], g_cntL[NCLS];
__device__ int   g_startR[NCLS + 1], g_startL[NCLS + 1];
__device__ int   g_memR[N], g_memL[N];
__device__ float g_posv[(size_t)N * MAXP];
__device__ int   g_posn[N];

// order-preserving float<->uint for atomicMax
__device__ __forceinline__ unsigned fenc(float x){
    unsigned u = __float_as_uint(x);
    return (u & 0x80000000u) ? ~u : (u | 0x80000000u);
}
__device__ __forceinline__ float fdec(unsigned e){
    unsigned u = (e & 0x80000000u) ? (e & 0x7FFFFFFFu) : ~e;
    return __uint_as_float(u);
}

// packed fp32x2 FMA (FFMA2) + broadcast-pack
__device__ __forceinline__ void ffma2(ull &d, ull a, ull b){
    asm("fma.rn.f32x2 %0, %1, %2, %0;" : "+l"(d) : "l"(a), "l"(b));
}
__device__ __forceinline__ ull dup2(float a){
    ull r; unsigned u = __float_as_uint(a);
    asm("mov.b64 %0, {%1, %1};" : "=l"(r) : "r"(u));
    return r;
}
__device__ __forceinline__ float f2lo(ull v){ return __uint_as_float((unsigned)v); }
__device__ __forceinline__ float f2hi(ull v){ return __uint_as_float((unsigned)(v >> 32)); }

// bin coordinate: t = clamp(800 - 800*s, 0, 1600)
__device__ __forceinline__ float binval(float s){
    return fminf(fmaxf(fmaf(s, -800.f, 800.f), 0.f), 1600.f);
}

// ---------------- kernel 0: counts + class CSR ----------------
__global__ void setup_kernel(const int* __restrict__ tr, const int* __restrict__ rl){
    __shared__ int cR[NCLS], cL[NCLS];
    __shared__ int wR[16], wL[16];
    int t = threadIdx.x;           // blockDim = 512 = NCLS
    cR[t] = 0; cL[t] = 0;
    __syncthreads();
    for (int i = t; i < N; i += 512){
        atomicAdd(&cR[tr[i]], 1);
        atomicAdd(&cL[rl[i]], 1);
    }
    __syncthreads();
    // parallel exclusive scan over 512 counts
    int lane = t & 31, warp = t >> 5;
    int vR = cR[t], vL = cL[t];
    g_cntR[t] = vR; g_cntL[t] = vL;
    int sR = vR, sL = vL;
#pragma unroll
    for (int o = 1; o < 32; o <<= 1){
        int uR = __shfl_up_sync(0xffffffffu, sR, o);
        int uL = __shfl_up_sync(0xffffffffu, sL, o);
        if (lane >= o){ sR += uR; sL += uL; }
    }
    if (lane == 31){ wR[warp] = sR; wL[warp] = sL; }
    __syncthreads();
    if (t == 0){
        int rR = 0, rL = 0;
        for (int w = 0; w < 16; w++){
            int a = wR[w], b = wL[w];
            wR[w] = rR; wL[w] = rL;
            rR += a; rL += b;
        }
        g_startR[NCLS] = rR; g_startL[NCLS] = rL;
    }
    __syncthreads();
    int excR = wR[warp] + sR - vR;
    int excL = wL[warp] + sL - vL;
    g_startR[t] = excR; g_startL[t] = excL;
    cR[t] = excR; cL[t] = excL;
    __syncthreads();
    for (int i = t; i < N; i += 512){
        int p = atomicAdd(&cR[tr[i]], 1); g_memR[p] = i;
        int q = atomicAdd(&cL[rl[i]], 1); g_memL[q] = i;
    }
}

// ---------------- pure GEMM: g_sim = A @ B^T ----------------
__global__ __launch_bounds__(256, 2) void gemm_nt(
    const float* __restrict__ A, const float* __restrict__ B)
{
    __shared__ __align__(16) float As[128][20];
    __shared__ __align__(16) float Bs[16][132];

    const int tid = threadIdx.x;
    const int tx  = tid & 15;
    const int ty  = tid >> 4;
    const int row0 = blockIdx.y * 128;
    const int col0 = blockIdx.x * 128;
    const int lr = tid >> 2;
    const int lk = (tid & 3) * 4;

    ull acc[8][4];
#pragma unroll
    for (int r = 0; r < 8; r++)
#pragma unroll
        for (int c = 0; c < 4; c++) acc[r][c] = 0ULL;

    const float* Ap0 = A + (size_t)(row0 + lr) * D + lk;
    const float* Ap1 = A + (size_t)(row0 + lr + 64) * D + lk;
    const float* Bp0 = B + (size_t)(col0 + lr) * D + lk;
    const float* Bp1 = B + (size_t)(col0 + lr + 64) * D + lk;

    float4 pa0 = *(const float4*)Ap0;
    float4 pa1 = *(const float4*)Ap1;
    float4 pb0 = *(const float4*)Bp0;
    float4 pb1 = *(const float4*)Bp1;

#pragma unroll
    for (int kc = 0; kc < D; kc += 16){
        __syncthreads();
        *(float4*)&As[lr][lk]      = pa0;
        *(float4*)&As[lr + 64][lk] = pa1;
        Bs[lk+0][lr] = pb0.x; Bs[lk+1][lr] = pb0.y;
        Bs[lk+2][lr] = pb0.z; Bs[lk+3][lr] = pb0.w;
        Bs[lk+0][lr+64] = pb1.x; Bs[lk+1][lr+64] = pb1.y;
        Bs[lk+2][lr+64] = pb1.z; Bs[lk+3][lr+64] = pb1.w;
        __syncthreads();
        if (kc < D - 16){
            pa0 = *(const float4*)(Ap0 + kc + 16);
            pa1 = *(const float4*)(Ap1 + kc + 16);
            pb0 = *(const float4*)(Bp0 + kc + 16);
            pb1 = *(const float4*)(Bp1 + kc + 16);
        }
#pragma unroll
        for (int kk = 0; kk < 16; kk++){
            ulonglong2 b01 = *(const ulonglong2*)&Bs[kk][tx * 8];
            ulonglong2 b23 = *(const ulonglong2*)&Bs[kk][tx * 8 + 4];
#pragma unroll
            for (int r = 0; r < 8; r++){
                ull a2 = dup2(As[ty * 8 + r][kk]);
                ffma2(acc[r][0], a2, b01.x);
                ffma2(acc[r][1], a2, b01.y);
                ffma2(acc[r][2], a2, b23.x);
                ffma2(acc[r][3], a2, b23.y);
            }
        }
    }

#pragma unroll
    for (int r = 0; r < 8; r++){
        float o[8];
#pragma unroll
        for (int c = 0; c < 4; c++){ o[2*c] = f2lo(acc[r][c]); o[2*c+1] = f2hi(acc[r][c]); }
        float* dst = g_sim + (size_t)(row0 + ty * 8 + r) * N + col0 + tx * 8;
        *(float4*)dst       = make_float4(o[0], o[1], o[2], o[3]);
        *(float4*)(dst + 4) = make_float4(o[4], o[5], o[6], o[7]);
    }
}

// ---------------- loss fix: extract pos sims, poison them in g_sim ----------------
__global__ void loss_fix(const int* __restrict__ tc, const int* __restrict__ tr){
    const int warp = threadIdx.x >> 5, lane = threadIdx.x & 31;
    const int i = blockIdx.x * 8 + warp;
    const int c = tc[i];
    const int s0 = g_startR[c], cnt = g_startR[c + 1] - s0;
    int ki = -1;
    for (int k = lane; k < cnt; k += 32)
        if (g_memR[s0 + k] == i) ki = k;
#pragma unroll
    for (int o = 16; o; o >>= 1) ki = max(ki, __shfl_xor_sync(0xffffffffu, ki, o));
    for (int k = lane; k < cnt; k += 32){
        int j = g_memR[s0 + k];
        float v = g_sim[(size_t)i * N + j];
        g_sim[(size_t)i * N + j] = -INFINITY;
        if (j != i){
            int slot = k - ((ki >= 0 && k > ki) ? 1 : 0);
            if (slot < MAXP) g_posv[(size_t)i * MAXP + slot] = v;
        }
    }
    if (lane == 0) g_posn[i] = min(cnt - (ki >= 0 ? 1 : 0), MAXP);
}

// ---------------- loss pass: per-row max then thresholded sums ----------------
__global__ __launch_bounds__(256) void loss_pass(
    const int* __restrict__ tc, const int* __restrict__ tr)
{
    __shared__ unsigned nme[8];
    __shared__ float nthr_s[8], pthr_s[8], accs[8];
    const int tid = threadIdx.x;
    const int row0 = blockIdx.x * 8;

    if (tid < 8){ nme[tid] = fenc(-INFINITY); accs[tid] = 0.f; }
    __syncthreads();

    float m[8];
#pragma unroll
    for (int r = 0; r < 8; r++) m[r] = -INFINITY;
    for (int it = 0; it < 4; it++){
        int j4 = tid + it * 256;
#pragma unroll
        for (int r = 0; r < 8; r++){
            float4 v = *((const float4*)(g_sim + (size_t)(row0 + r) * N) + j4);
            m[r] = fmaxf(m[r], fmaxf(fmaxf(v.x, v.y), fmaxf(v.z, v.w)));
        }
    }
#pragma unroll
    for (int r = 0; r < 8; r++) atomicMax(&nme[r], fenc(m[r]));
    __syncthreads();

    if (tid < 8){
        int i = row0 + tid;
        nthr_s[tid] = fdec(nme[tid]) + 0.1f;
        float pm = -INFINITY;
        int n = g_posn[i];
        for (int k = 0; k < n; k++) pm = fmaxf(pm, g_posv[(size_t)i * MAXP + k]);
        pthr_s[tid] = fmaxf(0.6f, pm) - 0.1f;
    }
    __syncthreads();

    float pt[8], a[8];
#pragma unroll
    for (int r = 0; r < 8; r++){ pt[r] = pthr_s[r]; a[r] = 0.f; }
    for (int it = 0; it < 4; it++){
        int j4 = tid + it * 256;
#pragma unroll
        for (int r = 0; r < 8; r++){
            float4 v = *((const float4*)(g_sim + (size_t)(row0 + r) * N) + j4);
            if (v.x > pt[r]) a[r] += v.x;
            if (v.y > pt[r]) a[r] += v.y;
            if (v.z > pt[r]) a[r] += v.z;
            if (v.w > pt[r]) a[r] += v.w;
        }
    }
#pragma unroll
    for (int r = 0; r < 8; r++) atomicAdd(&accs[r], a[r]);
    __syncthreads();

    if (tid < 8){
        int i = row0 + tid;
        float pl = 0.f, nthr = nthr_s[tid];
        int n = g_posn[i];
        for (int k = 0; k < n; k++){
            float v = g_posv[(size_t)i * MAXP + k];
            if (v < nthr) pl += 1.0f - v;
        }
        int npos = g_cntR[tc[i]] - ((tr[i] == tc[i]) ? 1 : 0);
        g_loss[i] = (npos > 0) ? accs[tid] + pl : 0.f;
    }
}

// ---------------- reward: rank-query FastAP (no histogram) ----------------
// H[b] = sum_j saturate((b+1) - t_j). AP only needs H_all at pos bins.
__global__ __launch_bounds__(256) void reward_ap(const int* __restrict__ rl){
    __shared__ float tP[MAXPR];           // pos t-values (excl diag)
    __shared__ float qv[2 * MAXPR];       // query thresholds per pos: e+1, e+2
    __shared__ float sQ[2 * MAXPR];       // H_all at the queries
    __shared__ int   np_s;
    __shared__ float s_ap;

    const int tid = threadIdx.x, lane = tid & 31;
    const int i = blockIdx.x;
    const int c = rl[i];
    const float* row = g_sim + (size_t)i * N;

    if (tid == 0){ np_s = 0; s_ap = 0.f; }
    if (tid < 2 * MAXPR) sQ[tid] = 0.f;
    __syncthreads();

    // gather positives via class CSR
    {
        int s0 = g_startL[c], cnt = g_startL[c + 1] - s0;
        if (tid < cnt){
            int j = g_memL[s0 + tid];
            if (j != i){
                float t = binval(row[j]);
                int k = atomicAdd(&np_s, 1);
                if (k < MAXPR){
                    tP[k] = t;
                    float e = floorf(t);
                    qv[2*k]   = e + 1.0f;
                    qv[2*k+1] = e + 2.0f;
                }
            }
        }
    }
    __syncthreads();
    const int npos = min(np_s, MAXPR);
    const int K = 2 * npos;

    // load this thread's 16 items; diagonal excluded via t = +inf
    float t[16];
#pragma unroll
    for (int it = 0; it < 4; it++){
        int j4 = tid + it * 256;
        float4 v = *((const float4*)row + j4);
        int j = j4 * 4;
        t[it*4+0] = (j+0 == i) ? 1e30f : binval(v.x);
        t[it*4+1] = (j+1 == i) ? 1e30f : binval(v.y);
        t[it*4+2] = (j+2 == i) ? 1e30f : binval(v.z);
        t[it*4+3] = (j+3 == i) ? 1e30f : binval(v.w);
    }

    // rank queries: sQ[k] = sum_j saturate(qv[k] - t_j)
    for (int k = 0; k < K; k++){
        float q = qv[k];
        float a = 0.f;
#pragma unroll
        for (int m = 0; m < 16; m++) a += __saturatef(q - t[m]);
#pragma unroll
        for (int o = 16; o; o >>= 1) a += __shfl_down_sync(0xffffffffu, a, o);
        if (lane == 0) atomicAdd(&sQ[k], a);
    }
    __syncthreads();

    // AP: per positive p, term = (1-fr)*HP0/HA0 + fr*HP1/HA1
    if (tid < npos){
        float tp = tP[tid];
        float u0 = qv[2*tid], u1 = qv[2*tid+1];
        float fr = tp - floorf(tp);
        float HP0 = 0.f, HP1 = 0.f;
        for (int q = 0; q < npos; q++){
            float tq = tP[q];
            HP0 += __saturatef(u0 - tq);
            HP1 += __saturatef(u1 - tq);
        }
        float HA0 = sQ[2*tid], HA1 = sQ[2*tid+1];
        float term = 0.f;
        if (HA0 > 0.f) term += (1.0f - fr) * HP0 / HA0;
        if (fr > 0.f && HA1 > 0.f) term += fr * HP1 / HA1;
        atomicAdd(&s_ap, term);
    }
    __syncthreads();
    if (tid == 0){
        int np = g_cntL[c] - 1;
        g_reward[i] = (np > 0) ? s_ap / (float)np : 0.f;
    }
}

// ---------------- final scalar ----------------
__global__ void final_kernel(float* __restrict__ out){
    __shared__ float red[32];
    float s = 0.f;
    for (int i = threadIdx.x; i < N; i += blockDim.x)
        s += g_loss[i] * (1.0f - g_reward[i]);
#pragma unroll
    for (int o = 16; o; o >>= 1) s += __shfl_down_sync(0xFFFFFFFFu, s, o);
    int warp = threadIdx.x >> 5, lane = threadIdx.x & 31;
    if (lane == 0) red[warp] = s;
    __syncthreads();
    if (warp == 0){
        s = (lane < (int)(blockDim.x >> 5)) ? red[lane] : 0.f;
#pragma unroll
        for (int o = 16; o; o >>= 1) s += __shfl_down_sync(0xFFFFFFFFu, s, o);
        if (lane == 0) out[0] = s / (float)N;
    }
}

// ---------------- launch ----------------
extern "C" void kernel_launch(void* const* d_in, const int* in_sizes, int n_in,
                              void* d_out, int out_size)
{
    const float* inputs_col    = (const float*)d_in[0];
    const int*   targets_col   = (const int*)  d_in[1];
    const float* inputs_row    = (const float*)d_in[2];
    const int*   targets_row   = (const int*)  d_in[3];
    const int*   reward_labels = (const int*)  d_in[4];
    float* out = (float*)d_out;

    setup_kernel<<<1, 512>>>(targets_row, reward_labels);
    gemm_nt<<<dim3(32, 32), 256>>>(inputs_col, inputs_row);
    loss_fix<<<512, 256>>>(targets_col, targets_row);
    loss_pass<<<512, 256>>>(targets_col, targets_row);
    gemm_nt<<<dim3(32, 32), 256>>>(inputs_col, inputs_col);
    reward_ap<<<4096, 256>>>(reward_labels);
    final_kernel<<<1, 256>>>(out);
}

// round 6
// speedup vs baseline: 5.2788x; 1.6478x over previous
#include <cuda_runtime.h>
#include <cuda_bf16.h>
#include <math.h>
#include <cstdint>

#define N 4096
#define D 128
#define NCLS 512
#define MAXP 128
#define MAXPR 64

typedef unsigned long long ull;

// ---- device scratch ----
__device__ float g_sim[(size_t)N * N];
__device__ float g_loss[N];
__device__ float g_reward[N];
__device__ int   g_cntR[NCLS], g_cntL[NCLS];
__device__ int   g_startR[NCLS + 1], g_startL[NCLS + 1];
__device__ int   g_memR[N], g_memL[N];
__device__ float g_posv[(size_t)N * MAXP];
__device__ int   g_posn[N];
__device__ __nv_bfloat16 g_colhi[N * D], g_collo[N * D];
__device__ __nv_bfloat16 g_rowhi[N * D], g_rowlo[N * D];

__device__ __forceinline__ unsigned fenc(float x){
    unsigned u = __float_as_uint(x);
    return (u & 0x80000000u) ? ~u : (u | 0x80000000u);
}
__device__ __forceinline__ float fdec(unsigned e){
    unsigned u = (e & 0x80000000u) ? (e & 0x7FFFFFFFu) : ~e;
    return __uint_as_float(u);
}
__device__ __forceinline__ float binval(float s){
    return fminf(fmaxf(fmaf(s, -800.f, 800.f), 0.f), 1600.f);
}
__device__ __forceinline__ uint32_t smem_u32(const void* p){
    uint32_t a;
    asm("{ .reg .u64 t; cvta.to.shared.u64 t, %1; cvt.u32.u64 %0, t; }" : "=r"(a) : "l"(p));
    return a;
}

// ---------------- split prep: fp32 -> bf16 hi/lo ----------------
__global__ void split_kernel(const float* __restrict__ col, const float* __restrict__ row){
    int i = blockIdx.x * 256 + threadIdx.x;   // grid 2048
    float c = col[i], r = row[i];
    __nv_bfloat16 ch = __float2bfloat16(c);
    __nv_bfloat16 rh = __float2bfloat16(r);
    g_colhi[i] = ch; g_collo[i] = __float2bfloat16(c - __bfloat162float(ch));
    g_rowhi[i] = rh; g_rowlo[i] = __float2bfloat16(r - __bfloat162float(rh));
}

// ---------------- tensor-core GEMM via mma.sync (bf16 split x3) ----------------
// 128x128 tile per CTA, 8 warps in 2x4 grid, warp tile 64x32.
#define SSTR 136   // bf16 elements per smem row (128 + 8 pad)

__global__ __launch_bounds__(256, 1) void gemm_mma(int useRowB){
    __shared__ __nv_bfloat16 sA[2][128][SSTR];   // [hi/lo][row][k]
    __shared__ __nv_bfloat16 sB[2][128][SSTR];

    const int tid  = threadIdx.x;
    const int wid  = tid >> 5;
    const int lane = tid & 31;
    const int row0 = blockIdx.y * 128;
    const int col0 = blockIdx.x * 128;

    const __nv_bfloat16* Bh = useRowB ? g_rowhi : g_colhi;
    const __nv_bfloat16* Bl = useRowB ? g_rowlo : g_collo;

    // load all operands (each matrix 128 rows x 16 float4)
#pragma unroll
    for (int it = 0; it < 8; it++){
        int u = tid + it * 256;
        int r = u >> 4, c = (u & 15) * 8;
        *(float4*)&sA[0][r][c] = *(const float4*)&g_colhi[(row0 + r) * D + c];
        *(float4*)&sA[1][r][c] = *(const float4*)&g_collo[(row0 + r) * D + c];
        *(float4*)&sB[0][r][c] = *(const float4*)&Bh[(col0 + r) * D + c];
        *(float4*)&sB[1][r][c] = *(const float4*)&Bl[(col0 + r) * D + c];
    }
    __syncthreads();

    const int wr = wid & 1;     // 0-1: 64-row half
    const int wc = wid >> 1;    // 0-3: 32-col quarter

    float c0[4][4], c1[4][4], c2[4][4], c3[4][4];
#pragma unroll
    for (int mf = 0; mf < 4; mf++)
#pragma unroll
        for (int nf = 0; nf < 4; nf++){
            c0[mf][nf] = 0.f; c1[mf][nf] = 0.f; c2[mf][nf] = 0.f; c3[mf][nf] = 0.f;
        }

    // segments: (A_hi,B_hi), (A_hi,B_lo), (A_lo,B_hi)
#pragma unroll
    for (int seg = 0; seg < 3; seg++){
        const int ai = (seg == 2) ? 1 : 0;
        const int bi = (seg == 1) ? 1 : 0;
#pragma unroll
        for (int ks = 0; ks < 8; ks++){
            const int k0 = ks * 16;
            // A fragments: 4 x ldmatrix.x4 (16x16 tiles)
            uint32_t a[4][4];
#pragma unroll
            for (int mf = 0; mf < 4; mf++){
                int trow = wr * 64 + mf * 16 + (lane & 15);
                int tcol = k0 + (lane >> 4) * 8;
                uint32_t addr = smem_u32(&sA[ai][trow][tcol]);
                asm volatile("ldmatrix.sync.aligned.m8n8.x4.shared.b16 {%0,%1,%2,%3}, [%4];"
                    : "=r"(a[mf][0]), "=r"(a[mf][1]), "=r"(a[mf][2]), "=r"(a[mf][3])
                    : "r"(addr));
            }
            // B fragments: 4 x ldmatrix.x2 (8n x 16k tiles)
            uint32_t b[4][2];
#pragma unroll
            for (int nf = 0; nf < 4; nf++){
                int trow = wc * 32 + nf * 8 + (lane & 7);
                int tcol = k0 + ((lane >> 3) & 1) * 8;
                uint32_t addr = smem_u32(&sB[bi][trow][tcol]);
                asm volatile("ldmatrix.sync.aligned.m8n8.x2.shared.b16 {%0,%1}, [%2];"
                    : "=r"(b[nf][0]), "=r"(b[nf][1]) : "r"(addr));
            }
#pragma unroll
            for (int mf = 0; mf < 4; mf++)
#pragma unroll
                for (int nf = 0; nf < 4; nf++){
                    asm volatile(
                        "mma.sync.aligned.m16n8k16.row.col.f32.bf16.bf16.f32 "
                        "{%0,%1,%2,%3}, {%4,%5,%6,%7}, {%8,%9}, {%0,%1,%2,%3};"
                        : "+f"(c0[mf][nf]), "+f"(c1[mf][nf]), "+f"(c2[mf][nf]), "+f"(c3[mf][nf])
                        : "r"(a[mf][0]), "r"(a[mf][1]), "r"(a[mf][2]), "r"(a[mf][3]),
                          "r"(b[nf][0]), "r"(b[nf][1]));
                }
        }
    }

    // epilogue
    const int g = lane >> 2, t = lane & 3;
#pragma unroll
    for (int mf = 0; mf < 4; mf++){
        int rA = row0 + wr * 64 + mf * 16 + g;
#pragma unroll
        for (int nf = 0; nf < 4; nf++){
            int cc = col0 + wc * 32 + nf * 8 + 2 * t;
            *(float2*)&g_sim[(size_t)rA * N + cc]       = make_float2(c0[mf][nf], c1[mf][nf]);
            *(float2*)&g_sim[(size_t)(rA + 8) * N + cc] = make_float2(c2[mf][nf], c3[mf][nf]);
        }
    }
}

// ---------------- kernel 0: counts + class CSR ----------------
__global__ void setup_kernel(const int* __restrict__ tr, const int* __restrict__ rl){
    __shared__ int cR[NCLS], cL[NCLS];
    __shared__ int wR[16], wL[16];
    int t = threadIdx.x;           // 512 = NCLS
    cR[t] = 0; cL[t] = 0;
    __syncthreads();
    for (int i = t; i < N; i += 512){
        atomicAdd(&cR[tr[i]], 1);
        atomicAdd(&cL[rl[i]], 1);
    }
    __syncthreads();
    int lane = t & 31, warp = t >> 5;
    int vR = cR[t], vL = cL[t];
    g_cntR[t] = vR; g_cntL[t] = vL;
    int sR = vR, sL = vL;
#pragma unroll
    for (int o = 1; o < 32; o <<= 1){
        int uR = __shfl_up_sync(0xffffffffu, sR, o);
        int uL = __shfl_up_sync(0xffffffffu, sL, o);
        if (lane >= o){ sR += uR; sL += uL; }
    }
    if (lane == 31){ wR[warp] = sR; wL[warp] = sL; }
    __syncthreads();
    if (t == 0){
        int rR = 0, rL = 0;
        for (int w = 0; w < 16; w++){
            int a = wR[w], b = wL[w];
            wR[w] = rR; wL[w] = rL;
            rR += a; rL += b;
        }
        g_startR[NCLS] = rR; g_startL[NCLS] = rL;
    }
    __syncthreads();
    int excR = wR[warp] + sR - vR;
    int excL = wL[warp] + sL - vL;
    g_startR[t] = excR; g_startL[t] = excL;
    cR[t] = excR; cL[t] = excL;
    __syncthreads();
    for (int i = t; i < N; i += 512){
        int p = atomicAdd(&cR[tr[i]], 1); g_memR[p] = i;
        int q = atomicAdd(&cL[rl[i]], 1); g_memL[q] = i;
    }
}

// ---------------- loss fix ----------------
__global__ void loss_fix(const int* __restrict__ tc, const int* __restrict__ tr){
    const int warp = threadIdx.x >> 5, lane = threadIdx.x & 31;
    const int i = blockIdx.x * 8 + warp;
    const int c = tc[i];
    const int s0 = g_startR[c], cnt = g_startR[c + 1] - s0;
    int ki = -1;
    for (int k = lane; k < cnt; k += 32)
        if (g_memR[s0 + k] == i) ki = k;
#pragma unroll
    for (int o = 16; o; o >>= 1) ki = max(ki, __shfl_xor_sync(0xffffffffu, ki, o));
    for (int k = lane; k < cnt; k += 32){
        int j = g_memR[s0 + k];
        float v = g_sim[(size_t)i * N + j];
        g_sim[(size_t)i * N + j] = -INFINITY;
        if (j != i){
            int slot = k - ((ki >= 0 && k > ki) ? 1 : 0);
            if (slot < MAXP) g_posv[(size_t)i * MAXP + slot] = v;
        }
    }
    if (lane == 0) g_posn[i] = min(cnt - (ki >= 0 ? 1 : 0), MAXP);
}

// ---------------- loss pass ----------------
__global__ __launch_bounds__(256) void loss_pass(
    const int* __restrict__ tc, const int* __restrict__ tr)
{
    __shared__ unsigned nme[8];
    __shared__ float nthr_s[8], pthr_s[8], accs[8];
    const int tid = threadIdx.x;
    const int row0 = blockIdx.x * 8;

    if (tid < 8){ nme[tid] = fenc(-INFINITY); accs[tid] = 0.f; }
    __syncthreads();

    float m[8];
#pragma unroll
    for (int r = 0; r < 8; r++) m[r] = -INFINITY;
    for (int it = 0; it < 4; it++){
        int j4 = tid + it * 256;
#pragma unroll
        for (int r = 0; r < 8; r++){
            float4 v = *((const float4*)(g_sim + (size_t)(row0 + r) * N) + j4);
            m[r] = fmaxf(m[r], fmaxf(fmaxf(v.x, v.y), fmaxf(v.z, v.w)));
        }
    }
#pragma unroll
    for (int r = 0; r < 8; r++) atomicMax(&nme[r], fenc(m[r]));
    __syncthreads();

    if (tid < 8){
        int i = row0 + tid;
        nthr_s[tid] = fdec(nme[tid]) + 0.1f;
        float pm = -INFINITY;
        int n = g_posn[i];
        for (int k = 0; k < n; k++) pm = fmaxf(pm, g_posv[(size_t)i * MAXP + k]);
        pthr_s[tid] = fmaxf(0.6f, pm) - 0.1f;
    }
    __syncthreads();

    float pt[8], a[8];
#pragma unroll
    for (int r = 0; r < 8; r++){ pt[r] = pthr_s[r]; a[r] = 0.f; }
    for (int it = 0; it < 4; it++){
        int j4 = tid + it * 256;
#pragma unroll
        for (int r = 0; r < 8; r++){
            float4 v = *((const float4*)(g_sim + (size_t)(row0 + r) * N) + j4);
            if (v.x > pt[r]) a[r] += v.x;
            if (v.y > pt[r]) a[r] += v.y;
            if (v.z > pt[r]) a[r] += v.z;
            if (v.w > pt[r]) a[r] += v.w;
        }
    }
#pragma unroll
    for (int r = 0; r < 8; r++) atomicAdd(&accs[r], a[r]);
    __syncthreads();

    if (tid < 8){
        int i = row0 + tid;
        float pl = 0.f, nthr = nthr_s[tid];
        int n = g_posn[i];
        for (int k = 0; k < n; k++){
            float v = g_posv[(size_t)i * MAXP + k];
            if (v < nthr) pl += 1.0f - v;
        }
        int npos = g_cntR[tc[i]] - ((tr[i] == tc[i]) ? 1 : 0);
        g_loss[i] = (npos > 0) ? accs[tid] + pl : 0.f;
    }
}

// ---------------- reward: rank-query FastAP ----------------
__global__ __launch_bounds__(256) void reward_ap(const int* __restrict__ rl){
    __shared__ float tP[MAXPR];
    __shared__ float qv[2 * MAXPR];
    __shared__ float sQ[2 * MAXPR];
    __shared__ int   np_s;
    __shared__ float s_ap;

    const int tid = threadIdx.x, lane = tid & 31;
    const int i = blockIdx.x;
    const int c = rl[i];
    const float* row = g_sim + (size_t)i * N;

    if (tid == 0){ np_s = 0; s_ap = 0.f; }
    if (tid < 2 * MAXPR) sQ[tid] = 0.f;
    __syncthreads();

    {
        int s0 = g_startL[c], cnt = g_startL[c + 1] - s0;
        if (tid < cnt){
            int j = g_memL[s0 + tid];
            if (j != i){
                float t = binval(row[j]);
                int k = atomicAdd(&np_s, 1);
                if (k < MAXPR){
                    tP[k] = t;
                    float e = floorf(t);
                    qv[2*k]   = e + 1.0f;
                    qv[2*k+1] = e + 2.0f;
                }
            }
        }
    }
    __syncthreads();
    const int npos = min(np_s, MAXPR);
    const int K = 2 * npos;

    float t[16];
#pragma unroll
    for (int it = 0; it < 4; it++){
        int j4 = tid + it * 256;
        float4 v = *((const float4*)row + j4);
        int j = j4 * 4;
        t[it*4+0] = (j+0 == i) ? 1e30f : binval(v.x);
        t[it*4+1] = (j+1 == i) ? 1e30f : binval(v.y);
        t[it*4+2] = (j+2 == i) ? 1e30f : binval(v.z);
        t[it*4+3] = (j+3 == i) ? 1e30f : binval(v.w);
    }

    for (int k = 0; k < K; k++){
        float q = qv[k];
        float a = 0.f;
#pragma unroll
        for (int m = 0; m < 16; m++) a += __saturatef(q - t[m]);
#pragma unroll
        for (int o = 16; o; o >>= 1) a += __shfl_down_sync(0xffffffffu, a, o);
        if (lane == 0) atomicAdd(&sQ[k], a);
    }
    __syncthreads();

    if (tid < npos){
        float tp = tP[tid];
        float u0 = qv[2*tid], u1 = qv[2*tid+1];
        float fr = tp - floorf(tp);
        float HP0 = 0.f, HP1 = 0.f;
        for (int q = 0; q < npos; q++){
            float tq = tP[q];
            HP0 += __saturatef(u0 - tq);
            HP1 += __saturatef(u1 - tq);
        }
        float HA0 = sQ[2*tid], HA1 = sQ[2*tid+1];
        float term = 0.f;
        if (HA0 > 0.f) term += (1.0f - fr) * HP0 / HA0;
        if (fr > 0.f && HA1 > 0.f) term += fr * HP1 / HA1;
        atomicAdd(&s_ap, term);
    }
    __syncthreads();
    if (tid == 0){
        int np = g_cntL[c] - 1;
        g_reward[i] = (np > 0) ? s_ap / (float)np : 0.f;
    }
}

// ---------------- final scalar ----------------
__global__ void final_kernel(float* __restrict__ out){
    __shared__ float red[32];
    float s = 0.f;
    for (int i = threadIdx.x; i < N; i += blockDim.x)
        s += g_loss[i] * (1.0f - g_reward[i]);
#pragma unroll
    for (int o = 16; o; o >>= 1) s += __shfl_down_sync(0xFFFFFFFFu, s, o);
    int warp = threadIdx.x >> 5, lane = threadIdx.x & 31;
    if (lane == 0) red[warp] = s;
    __syncthreads();
    if (warp == 0){
        s = (lane < (int)(blockDim.x >> 5)) ? red[lane] : 0.f;
#pragma unroll
        for (int o = 16; o; o >>= 1) s += __shfl_down_sync(0xFFFFFFFFu, s, o);
        if (lane == 0) out[0] = s / (float)N;
    }
}

// ---------------- launch ----------------
extern "C" void kernel_launch(void* const* d_in, const int* in_sizes, int n_in,
                              void* d_out, int out_size)
{
    const float* inputs_col    = (const float*)d_in[0];
    const int*   targets_col   = (const int*)  d_in[1];
    const float* inputs_row    = (const float*)d_in[2];
    const int*   targets_row   = (const int*)  d_in[3];
    const int*   reward_labels = (const int*)  d_in[4];
    float* out = (float*)d_out;

    setup_kernel<<<1, 512>>>(targets_row, reward_labels);
    split_kernel<<<2048, 256>>>(inputs_col, inputs_row);
    gemm_mma<<<dim3(32, 32), 256>>>(1);     // col @ row^T
    loss_fix<<<512, 256>>>(targets_col, targets_row);
    loss_pass<<<512, 256>>>(targets_col, targets_row);
    gemm_mma<<<dim3(32, 32), 256>>>(0);     // col @ col^T
    reward_ap<<<4096, 256>>>(reward_labels);
    final_kernel<<<1, 256>>>(out);
}

// round 7
// speedup vs baseline: 5.4546x; 1.0333x over previous
#include <cuda_runtime.h>
#include <cuda_bf16.h>
#include <math.h>
#include <cstdint>

#define N 4096
#define D 128
#define NCLS 512
#define MAXPR 64
#define ENC_NINF 0x007FFFFFu

typedef unsigned long long ull;

// ---- device scratch ----
__device__ float g_sim[(size_t)N * N];
__device__ float g_loss[N];
__device__ float g_reward[N];
__device__ int   g_cntR[NCLS], g_cntL[NCLS];
__device__ int   g_startL[NCLS + 1];
__device__ int   g_memL[N];
__device__ unsigned g_pmax[N], g_nmax[N];
__device__ __nv_bfloat16 g_colhi[N * D], g_collo[N * D];
__device__ __nv_bfloat16 g_rowhi[N * D], g_rowlo[N * D];

__device__ __forceinline__ unsigned fenc(float x){
    unsigned u = __float_as_uint(x);
    return (u & 0x80000000u) ? ~u : (u | 0x80000000u);
}
__device__ __forceinline__ float fdec(unsigned e){
    unsigned u = (e & 0x80000000u) ? (e & 0x7FFFFFFFu) : ~e;
    return __uint_as_float(u);
}
__device__ __forceinline__ float binval(float s){
    return fminf(fmaxf(fmaf(s, -800.f, 800.f), 0.f), 1600.f);
}
__device__ __forceinline__ uint32_t smem_u32(const void* p){
    uint32_t a;
    asm("{ .reg .u64 t; cvta.to.shared.u64 t, %1; cvt.u32.u64 %0, t; }" : "=r"(a) : "l"(p));
    return a;
}

// ---------------- split prep ----------------
__global__ void split_kernel(const float* __restrict__ col, const float* __restrict__ row){
    int i = blockIdx.x * 256 + threadIdx.x;
    float c = col[i], r = row[i];
    __nv_bfloat16 ch = __float2bfloat16(c);
    __nv_bfloat16 rh = __float2bfloat16(r);
    g_colhi[i] = ch; g_collo[i] = __float2bfloat16(c - __bfloat162float(ch));
    g_rowhi[i] = rh; g_rowlo[i] = __float2bfloat16(r - __bfloat162float(rh));
}

// ================= shared MMA core (macro-free helpers) =================
#define SSTR 136

struct Frag { float c0[4][4], c1[4][4], c2[4][4], c3[4][4]; };

__device__ __forceinline__ void mma_tile(
    Frag& F, const __nv_bfloat16 (*sA)[128][SSTR], const __nv_bfloat16 (*sB)[128][SSTR],
    int wr, int wc, int lane)
{
#pragma unroll
    for (int mf = 0; mf < 4; mf++)
#pragma unroll
        for (int nf = 0; nf < 4; nf++){
            F.c0[mf][nf] = 0.f; F.c1[mf][nf] = 0.f; F.c2[mf][nf] = 0.f; F.c3[mf][nf] = 0.f;
        }
#pragma unroll
    for (int seg = 0; seg < 3; seg++){
        const int ai = (seg == 2) ? 1 : 0;
        const int bi = (seg == 1) ? 1 : 0;
#pragma unroll
        for (int ks = 0; ks < 8; ks++){
            const int k0 = ks * 16;
            uint32_t a[4][4];
#pragma unroll
            for (int mf = 0; mf < 4; mf++){
                int trow = wr * 64 + mf * 16 + (lane & 15);
                int tcol = k0 + (lane >> 4) * 8;
                uint32_t addr = smem_u32(&sA[ai][trow][tcol]);
                asm volatile("ldmatrix.sync.aligned.m8n8.x4.shared.b16 {%0,%1,%2,%3}, [%4];"
                    : "=r"(a[mf][0]), "=r"(a[mf][1]), "=r"(a[mf][2]), "=r"(a[mf][3])
                    : "r"(addr));
            }
            uint32_t b[4][2];
#pragma unroll
            for (int nf = 0; nf < 4; nf++){
                int trow = wc * 32 + nf * 8 + (lane & 7);
                int tcol = k0 + ((lane >> 3) & 1) * 8;
                uint32_t addr = smem_u32(&sB[bi][trow][tcol]);
                asm volatile("ldmatrix.sync.aligned.m8n8.x2.shared.b16 {%0,%1}, [%2];"
                    : "=r"(b[nf][0]), "=r"(b[nf][1]) : "r"(addr));
            }
#pragma unroll
            for (int mf = 0; mf < 4; mf++)
#pragma unroll
                for (int nf = 0; nf < 4; nf++){
                    asm volatile(
                        "mma.sync.aligned.m16n8k16.row.col.f32.bf16.bf16.f32 "
                        "{%0,%1,%2,%3}, {%4,%5,%6,%7}, {%8,%9}, {%0,%1,%2,%3};"
                        : "+f"(F.c0[mf][nf]), "+f"(F.c1[mf][nf]),
                          "+f"(F.c2[mf][nf]), "+f"(F.c3[mf][nf])
                        : "r"(a[mf][0]), "r"(a[mf][1]), "r"(a[mf][2]), "r"(a[mf][3]),
                          "r"(b[nf][0]), "r"(b[nf][1]));
                }
        }
    }
}

// ---------------- loss GEMM: sim = col @ row^T, epilogue computes maxima ----------------
__global__ __launch_bounds__(256, 1) void gemm_loss(
    const int* __restrict__ tc, const int* __restrict__ tr)
{
    __shared__ __nv_bfloat16 sA[2][128][SSTR];
    __shared__ __nv_bfloat16 sB[2][128][SSTR];
    __shared__ int tcs[128], trs[128];
    __shared__ unsigned pme[128], nme[128];

    const int tid  = threadIdx.x;
    const int wid  = tid >> 5;
    const int lane = tid & 31;
    const int row0 = blockIdx.y * 128;
    const int col0 = blockIdx.x * 128;

    if (tid < 128){
        tcs[tid] = tc[row0 + tid];
        trs[tid] = tr[col0 + tid];
        pme[tid] = ENC_NINF; nme[tid] = ENC_NINF;
    }
#pragma unroll
    for (int it = 0; it < 8; it++){
        int u = tid + it * 256;
        int r = u >> 4, c = (u & 15) * 8;
        *(float4*)&sA[0][r][c] = *(const float4*)&g_colhi[(row0 + r) * D + c];
        *(float4*)&sA[1][r][c] = *(const float4*)&g_collo[(row0 + r) * D + c];
        *(float4*)&sB[0][r][c] = *(const float4*)&g_rowhi[(col0 + r) * D + c];
        *(float4*)&sB[1][r][c] = *(const float4*)&g_rowlo[(col0 + r) * D + c];
    }
    __syncthreads();

    const int wr = wid & 1, wc = wid >> 1;
    Frag F;
    mma_tile(F, sA, sB, wr, wc, lane);

    const int g = lane >> 2, t = lane & 3;

    // labels for this thread's 8 columns
    int lab[8];
#pragma unroll
    for (int nf = 0; nf < 4; nf++){
        lab[nf*2]   = trs[wc * 32 + nf * 8 + 2 * t];
        lab[nf*2+1] = trs[wc * 32 + nf * 8 + 2 * t + 1];
    }

    // store + per-row label-checked maxima
#pragma unroll
    for (int mf = 0; mf < 4; mf++){
#pragma unroll
        for (int hf = 0; hf < 2; hf++){
            int lrow = wr * 64 + mf * 16 + hf * 8 + g;
            int gi   = row0 + lrow;
            int tcv  = tcs[lrow];
            float pm = -INFINITY, nm = -INFINITY;
#pragma unroll
            for (int nf = 0; nf < 4; nf++){
                int ccb = col0 + wc * 32 + nf * 8 + 2 * t;
                float v0 = hf ? F.c2[mf][nf] : F.c0[mf][nf];
                float v1 = hf ? F.c3[mf][nf] : F.c1[mf][nf];
                if (lab[nf*2] == tcv){ if (ccb != gi) pm = fmaxf(pm, v0); }
                else nm = fmaxf(nm, v0);
                if (lab[nf*2+1] == tcv){ if (ccb + 1 != gi) pm = fmaxf(pm, v1); }
                else nm = fmaxf(nm, v1);
            }
            pm = fmaxf(pm, __shfl_xor_sync(0xffffffffu, pm, 1));
            pm = fmaxf(pm, __shfl_xor_sync(0xffffffffu, pm, 2));
            nm = fmaxf(nm, __shfl_xor_sync(0xffffffffu, nm, 1));
            nm = fmaxf(nm, __shfl_xor_sync(0xffffffffu, nm, 2));
            if (t == 0){
                atomicMax(&pme[lrow], fenc(pm));
                atomicMax(&nme[lrow], fenc(nm));
            }
#pragma unroll
            for (int nf = 0; nf < 4; nf++){
                int cc = col0 + wc * 32 + nf * 8 + 2 * t;
                float v0 = hf ? F.c2[mf][nf] : F.c0[mf][nf];
                float v1 = hf ? F.c3[mf][nf] : F.c1[mf][nf];
                *(float2*)&g_sim[(size_t)gi * N + cc] = make_float2(v0, v1);
            }
        }
    }
    __syncthreads();
    if (tid < 128){
        atomicMax(&g_pmax[row0 + tid], pme[tid]);
        atomicMax(&g_nmax[row0 + tid], nme[tid]);
    }
}

// ---------------- symmetric GEMM: sim = col @ col^T, triangular grid ----------------
__global__ __launch_bounds__(256, 1) void gemm_sym(){
    __shared__ __nv_bfloat16 sA[2][128][SSTR];
    __shared__ __nv_bfloat16 sB[2][128][SSTR];

    const int tid  = threadIdx.x;
    const int wid  = tid >> 5;
    const int lane = tid & 31;

    int b = blockIdx.x, bx = 0;
    while ((bx + 1) * (bx + 2) / 2 <= b) bx++;
    int by = b - bx * (bx + 1) / 2;
    const int row0 = by * 128;
    const int col0 = bx * 128;

#pragma unroll
    for (int it = 0; it < 8; it++){
        int u = tid + it * 256;
        int r = u >> 4, c = (u & 15) * 8;
        *(float4*)&sA[0][r][c] = *(const float4*)&g_colhi[(row0 + r) * D + c];
        *(float4*)&sA[1][r][c] = *(const float4*)&g_collo[(row0 + r) * D + c];
        *(float4*)&sB[0][r][c] = *(const float4*)&g_colhi[(col0 + r) * D + c];
        *(float4*)&sB[1][r][c] = *(const float4*)&g_collo[(col0 + r) * D + c];
    }
    __syncthreads();

    const int wr = wid & 1, wc = wid >> 1;
    Frag F;
    mma_tile(F, sA, sB, wr, wc, lane);

    const int g = lane >> 2, t = lane & 3;

    // direct write
#pragma unroll
    for (int mf = 0; mf < 4; mf++){
        int rA = row0 + wr * 64 + mf * 16 + g;
#pragma unroll
        for (int nf = 0; nf < 4; nf++){
            int cc = col0 + wc * 32 + nf * 8 + 2 * t;
            *(float2*)&g_sim[(size_t)rA * N + cc]       = make_float2(F.c0[mf][nf], F.c1[mf][nf]);
            *(float2*)&g_sim[(size_t)(rA + 8) * N + cc] = make_float2(F.c2[mf][nf], F.c3[mf][nf]);
        }
    }

    if (bx != by){
        // stage transpose in smem (reuse sA), then coalesced write
        float* stg = (float*)&sA[0][0][0];   // [128][132]
        __syncthreads();
#pragma unroll
        for (int mf = 0; mf < 4; mf++){
            int rr = wr * 64 + mf * 16 + g;
#pragma unroll
            for (int nf = 0; nf < 4; nf++){
                int cc = wc * 32 + nf * 8 + 2 * t;
                stg[(cc    ) * 132 + rr]     = F.c0[mf][nf];
                stg[(cc + 1) * 132 + rr]     = F.c1[mf][nf];
                stg[(cc    ) * 132 + rr + 8] = F.c2[mf][nf];
                stg[(cc + 1) * 132 + rr + 8] = F.c3[mf][nf];
            }
        }
        __syncthreads();
#pragma unroll
        for (int it = 0; it < 16; it++){
            int u = tid + it * 256;
            int r = u >> 5, c4 = (u & 31) * 4;
            float4 v = *(const float4*)&stg[r * 132 + c4];
            *(float4*)&g_sim[(size_t)(col0 + r) * N + row0 + c4] = v;
        }
    }
}

// ---------------- setup: counts + reward-label CSR + maxima init ----------------
__global__ void setup_kernel(const int* __restrict__ tr, const int* __restrict__ rl){
    __shared__ int cR[NCLS], cL[NCLS];
    __shared__ int wL[16];
    int t = threadIdx.x;           // 512 = NCLS
    cR[t] = 0; cL[t] = 0;
    __syncthreads();
    for (int i = t; i < N; i += 512){
        atomicAdd(&cR[tr[i]], 1);
        atomicAdd(&cL[rl[i]], 1);
        g_pmax[i] = ENC_NINF;
        g_nmax[i] = ENC_NINF;
    }
    __syncthreads();
    int lane = t & 31, warp = t >> 5;
    g_cntR[t] = cR[t];
    int vL = cL[t];
    g_cntL[t] = vL;
    int sL = vL;
#pragma unroll
    for (int o = 1; o < 32; o <<= 1){
        int uL = __shfl_up_sync(0xffffffffu, sL, o);
        if (lane >= o) sL += uL;
    }
    if (lane == 31) wL[warp] = sL;
    __syncthreads();
    if (t == 0){
        int rL = 0;
        for (int w = 0; w < 16; w++){ int a = wL[w]; wL[w] = rL; rL += a; }
        g_startL[NCLS] = rL;
    }
    __syncthreads();
    int excL = wL[warp] + sL - vL;
    g_startL[t] = excL;
    cL[t] = excL;
    __syncthreads();
    for (int i = t; i < N; i += 512){
        int q = atomicAdd(&cL[rl[i]], 1); g_memL[q] = i;
    }
}

// ---------------- loss: single streaming pass ----------------
__global__ __launch_bounds__(256) void loss_pass(
    const int* __restrict__ tc, const int* __restrict__ tr)
{
    __shared__ int labs[N];          // 16 KB
    __shared__ float nthr_s[8], pthr_s[8], accs[8];
    __shared__ int tcs[8];
    const int tid = threadIdx.x;
    const int row0 = blockIdx.x * 8;

    for (int j = tid; j < N; j += 256) labs[j] = tr[j];
    if (tid < 8){
        int i = row0 + tid;
        nthr_s[tid] = fdec(g_nmax[i]) + 0.1f;
        pthr_s[tid] = fmaxf(0.6f, fdec(g_pmax[i])) - 0.1f;
        tcs[tid]    = tc[i];
        accs[tid]   = 0.f;
    }
    __syncthreads();

    float a[8];
    float nt[8], pt[8]; int tcr[8];
#pragma unroll
    for (int r = 0; r < 8; r++){ a[r] = 0.f; nt[r] = nthr_s[r]; pt[r] = pthr_s[r]; tcr[r] = tcs[r]; }

    for (int it = 0; it < 4; it++){
        int j4 = tid + it * 256;
        int4 lb = *(const int4*)&labs[j4 * 4];
#pragma unroll
        for (int r = 0; r < 8; r++){
            int gi = row0 + r;
            float4 v = *((const float4*)(g_sim + (size_t)gi * N) + j4);
            int j = j4 * 4;
            if (lb.x == tcr[r]){ if (j   != gi && v.x < nt[r]) a[r] += 1.0f - v.x; }
            else if (v.x > pt[r]) a[r] += v.x;
            if (lb.y == tcr[r]){ if (j+1 != gi && v.y < nt[r]) a[r] += 1.0f - v.y; }
            else if (v.y > pt[r]) a[r] += v.y;
            if (lb.z == tcr[r]){ if (j+2 != gi && v.z < nt[r]) a[r] += 1.0f - v.z; }
            else if (v.z > pt[r]) a[r] += v.z;
            if (lb.w == tcr[r]){ if (j+3 != gi && v.w < nt[r]) a[r] += 1.0f - v.w; }
            else if (v.w > pt[r]) a[r] += v.w;
        }
    }
#pragma unroll
    for (int r = 0; r < 8; r++) atomicAdd(&accs[r], a[r]);
    __syncthreads();
    if (tid < 8){
        int i = row0 + tid;
        int npos = g_cntR[tcs[tid]] - ((tr[i] == tcs[tid]) ? 1 : 0);
        g_loss[i] = (npos > 0) ? accs[tid] : 0.f;
    }
}

// ---------------- reward: rank-query FastAP ----------------
__global__ __launch_bounds__(256) void reward_ap(const int* __restrict__ rl){
    __shared__ float tP[MAXPR];
    __shared__ float qv[2 * MAXPR];
    __shared__ float sQ[2 * MAXPR];
    __shared__ int   np_s;
    __shared__ float s_ap;

    const int tid = threadIdx.x, lane = tid & 31;
    const int i = blockIdx.x;
    const int c = rl[i];
    const float* row = g_sim + (size_t)i * N;

    if (tid == 0){ np_s = 0; s_ap = 0.f; }
    if (tid < 2 * MAXPR) sQ[tid] = 0.f;
    __syncthreads();

    {
        int s0 = g_startL[c], cnt = g_startL[c + 1] - s0;
        if (tid < cnt){
            int j = g_memL[s0 + tid];
            if (j != i){
                float t = binval(row[j]);
                int k = atomicAdd(&np_s, 1);
                if (k < MAXPR){
                    tP[k] = t;
                    float e = floorf(t);
                    qv[2*k]   = e + 1.0f;
                    qv[2*k+1] = e + 2.0f;
                }
            }
        }
    }
    __syncthreads();
    const int npos = min(np_s, MAXPR);
    const int K = 2 * npos;

    float t[16];
#pragma unroll
    for (int it = 0; it < 4; it++){
        int j4 = tid + it * 256;
        float4 v = *((const float4*)row + j4);
        int j = j4 * 4;
        t[it*4+0] = (j+0 == i) ? 1e30f : binval(v.x);
        t[it*4+1] = (j+1 == i) ? 1e30f : binval(v.y);
        t[it*4+2] = (j+2 == i) ? 1e30f : binval(v.z);
        t[it*4+3] = (j+3 == i) ? 1e30f : binval(v.w);
    }

    for (int k = 0; k < K; k++){
        float q = qv[k];
        float a = 0.f;
#pragma unroll
        for (int m = 0; m < 16; m++) a += __saturatef(q - t[m]);
#pragma unroll
        for (int o = 16; o; o >>= 1) a += __shfl_down_sync(0xffffffffu, a, o);
        if (lane == 0) atomicAdd(&sQ[k], a);
    }
    __syncthreads();

    if (tid < npos){
        float tp = tP[tid];
        float u0 = qv[2*tid], u1 = qv[2*tid+1];
        float fr = tp - floorf(tp);
        float HP0 = 0.f, HP1 = 0.f;
        for (int q = 0; q < npos; q++){
            float tq = tP[q];
            HP0 += __saturatef(u0 - tq);
            HP1 += __saturatef(u1 - tq);
        }
        float HA0 = sQ[2*tid], HA1 = sQ[2*tid+1];
        float term = 0.f;
        if (HA0 > 0.f) term += (1.0f - fr) * HP0 / HA0;
        if (fr > 0.f && HA1 > 0.f) term += fr * HP1 / HA1;
        atomicAdd(&s_ap, term);
    }
    __syncthreads();
    if (tid == 0){
        int np = g_cntL[c] - 1;
        g_reward[i] = (np > 0) ? s_ap / (float)np : 0.f;
    }
}

// ---------------- final scalar ----------------
__global__ void final_kernel(float* __restrict__ out){
    __shared__ float red[32];
    float s = 0.f;
    for (int i = threadIdx.x; i < N; i += blockDim.x)
        s += g_loss[i] * (1.0f - g_reward[i]);
#pragma unroll
    for (int o = 16; o; o >>= 1) s += __shfl_down_sync(0xFFFFFFFFu, s, o);
    int warp = threadIdx.x >> 5, lane = threadIdx.x & 31;
    if (lane == 0) red[warp] = s;
    __syncthreads();
    if (warp == 0){
        s = (lane < (int)(blockDim.x >> 5)) ? red[lane] : 0.f;
#pragma unroll
        for (int o = 16; o; o >>= 1) s += __shfl_down_sync(0xFFFFFFFFu, s, o);
        if (lane == 0) out[0] = s / (float)N;
    }
}

// ---------------- launch ----------------
extern "C" void kernel_launch(void* const* d_in, const int* in_sizes, int n_in,
                              void* d_out, int out_size)
{
    const float* inputs_col    = (const float*)d_in[0];
    const int*   targets_col   = (const int*)  d_in[1];
    const float* inputs_row    = (const float*)d_in[2];
    const int*   targets_row   = (const int*)  d_in[3];
    const int*   reward_labels = (const int*)  d_in[4];
    float* out = (float*)d_out;

    setup_kernel<<<1, 512>>>(targets_row, reward_labels);
    split_kernel<<<2048, 256>>>(inputs_col, inputs_row);
    gemm_loss<<<dim3(32, 32), 256>>>(targets_col, targets_row);
    loss_pass<<<512, 256>>>(targets_col, targets_row);
    gemm_sym<<<528, 256>>>();
    reward_ap<<<4096, 256>>>(reward_labels);
    final_kernel<<<1, 256>>>(out);
}